// round 12
// baseline (speedup 1.0000x reference)
#include <cuda_runtime.h>
#include <cuda_fp16.h>

#define N_NODES 100000
#define N_EDGES 3200000
#define IN_DIM 128
#define HID 64
#define OUT_DIM 32
#define N_LAYERS 3

#define NBLK ((N_NODES + 255) / 256)   // 391 scan blocks

// Scratch: device globals (alloc-free, graph-capture safe; zero-init at load)
__device__ float  g_hA[N_NODES * HID];
__device__ float  g_hB[N_NODES * HID];
__device__ float  g_hsum[N_NODES * HID];
__device__ __half g_hHalf[N_NODES * HID];   // fp16 copy of current h for gather
__device__ int2   g_es[N_EDGES];            // {src, weight_bits} grouped by dst
__device__ int    g_cnt[N_NODES];           // left zeroed at end of every call
__device__ int    g_rowptr[N_NODES + 1];
__device__ int    g_ofs[N_NODES];
__device__ int    g_bsum[NBLK];
__device__ int    g_boff[NBLK];

// ---------------------------------------------------------------------------
// Per-warp dtype detect: int64 elements (values < 2^31) have zero odd words.
// ---------------------------------------------------------------------------
__device__ __forceinline__ bool warp_is64(const int* ei32, int i) {
    return __all_sync(0xffffffffu, ei32[2 * i + 1] == 0);
}

// ---------------------------------------------------------------------------
// Histogram of dst (fused dtype detect). g_cnt must enter zeroed.
// ---------------------------------------------------------------------------
__global__ void hist_kernel(const void* __restrict__ ei) {
    int i = blockIdx.x * blockDim.x + threadIdx.x;
    if (i >= N_EDGES) return;
    bool is64 = warp_is64((const int*)ei, i);
    int dst = is64 ? (int)((const long long*)ei)[(long long)N_EDGES + i]
                   : ((const int*)ei)[N_EDGES + i];
    atomicAdd(&g_cnt[dst], 1);
}

// ---------------------------------------------------------------------------
// 3-phase exclusive scan of g_cnt -> g_rowptr / g_ofs
// ---------------------------------------------------------------------------
__global__ void scan1_kernel() {
    __shared__ int s[256];
    int i = blockIdx.x * 256 + threadIdx.x;
    s[threadIdx.x] = (i < N_NODES) ? g_cnt[i] : 0;
    __syncthreads();
    for (int off = 128; off > 0; off >>= 1) {
        if (threadIdx.x < off) s[threadIdx.x] += s[threadIdx.x + off];
        __syncthreads();
    }
    if (threadIdx.x == 0) g_bsum[blockIdx.x] = s[0];
}

__global__ void scan2_kernel() {
    __shared__ int s[512];
    int t = threadIdx.x;
    int v0 = (t < NBLK) ? g_bsum[t] : 0;
    s[t] = v0;
    __syncthreads();
    for (int off = 1; off < 512; off <<= 1) {
        int v = (t >= off) ? s[t - off] : 0;
        __syncthreads();
        s[t] += v;
        __syncthreads();
    }
    if (t < NBLK) g_boff[t] = s[t] - v0;   // exclusive
    if (t == 511) g_rowptr[N_NODES] = N_EDGES;
}

__global__ void scan3_kernel() {
    __shared__ int s[256];
    int t = threadIdx.x;
    int i = blockIdx.x * 256 + t;
    int v0 = (i < N_NODES) ? g_cnt[i] : 0;
    s[t] = v0;
    __syncthreads();
    for (int off = 1; off < 256; off <<= 1) {
        int v = (t >= off) ? s[t - off] : 0;
        __syncthreads();
        s[t] += v;
        __syncthreads();
    }
    if (i < N_NODES) {
        int start = g_boff[blockIdx.x] + s[t] - v0;
        g_rowptr[i] = start;
        g_ofs[i]    = start;
        g_cnt[i]    = 0;     // restore invariant for the next call/replay
    }
}

// ---------------------------------------------------------------------------
// Bucket-place edges by dst: es[p] = {src, weight_bits}
// ---------------------------------------------------------------------------
__global__ void sort_kernel(const void* __restrict__ ei,
                            const float* __restrict__ ew) {
    int i = blockIdx.x * blockDim.x + threadIdx.x;
    if (i >= N_EDGES) return;
    bool is64 = warp_is64((const int*)ei, i);
    int src, dst;
    if (is64) {
        src = (int)((const long long*)ei)[i];
        dst = (int)((const long long*)ei)[(long long)N_EDGES + i];
    } else {
        src = ((const int*)ei)[i];
        dst = ((const int*)ei)[N_EDGES + i];
    }
    int p = atomicAdd(&g_ofs[dst], 1);
    g_es[p] = make_int2(src, __float_as_int(ew[i]));
}

// ---------------------------------------------------------------------------
// Gather-aggregate: hsum[n] = h[n] + sum_{e in CSR row n} hHalf[src_e] * w_e
// One warp per node. Per 32-edge tile: lane l holds edge record es[beg+base+l]
// (one coalesced load). Tile processed in two 16-edge chunks; each chunk runs
// three explicit phases — shfl all 8 {src,w} per half, issue all 8 row loads
// into a register array (guaranteed MLP=8, no serial LDG->FMA dependency),
// then FMA. Out-of-range positions padded with w=0 (src=0 reads a valid row,
// contributes nothing) so the chunk is branch-free.
// ---------------------------------------------------------------------------
__device__ __forceinline__ void fma_row(float4& acc, uint2 r, float w) {
    __half2 h01 = *reinterpret_cast<__half2*>(&r.x);
    __half2 h23 = *reinterpret_cast<__half2*>(&r.y);
    float2 f01 = __half22float2(h01);
    float2 f23 = __half22float2(h23);
    acc.x += f01.x * w; acc.y += f01.y * w;
    acc.z += f23.x * w; acc.w += f23.y * w;
}

__global__ __launch_bounds__(256)
void gather_kernel(const float* __restrict__ h, float* __restrict__ hsum) {
    int gwarp = (blockIdx.x * 256 + threadIdx.x) >> 5;
    if (gwarp >= N_NODES) return;
    int lane = threadIdx.x & 31;
    int half = lane >> 4;
    int c    = lane & 15;
    int n    = gwarp;

    int beg = g_rowptr[n];
    int cnt = g_rowptr[n + 1] - beg;

    const uint2* hh = (const uint2*)g_hHalf;   // 16 uint2 per row

    float4 a0 = make_float4(0.f, 0.f, 0.f, 0.f);
    float4 a1 = make_float4(0.f, 0.f, 0.f, 0.f);
    float4 a2 = make_float4(0.f, 0.f, 0.f, 0.f);
    float4 a3 = make_float4(0.f, 0.f, 0.f, 0.f);

    for (int base = 0; base < cnt; base += 32) {
        int2 m = (base + lane < cnt) ? g_es[beg + base + lane]
                                     : make_int2(0, 0);   // w=0 padding
        #pragma unroll
        for (int chunk = 0; chunk < 2; chunk++) {
            // phase 1: distribute {src, w} for this half's 8 edges
            int   s[8];
            float w[8];
            #pragma unroll
            for (int j = 0; j < 8; j++) {
                int pos = chunk * 16 + j * 2 + half;
                s[j] = __shfl_sync(0xffffffffu, m.x, pos);
                w[j] = __int_as_float(__shfl_sync(0xffffffffu, m.y, pos));
            }
            // phase 2: issue all 8 row loads (8 outstanding L2 requests)
            uint2 r[8];
            #pragma unroll
            for (int j = 0; j < 8; j++)
                r[j] = hh[(size_t)s[j] * 16 + c];
            // phase 3: accumulate
            #pragma unroll
            for (int j = 0; j < 8; j++)
                fma_row((j & 3) == 0 ? a0 : (j & 3) == 1 ? a1
                                     : (j & 3) == 2 ? a2 : a3,
                        r[j], w[j]);
        }
    }

    a0.x += a1.x + a2.x + a3.x;
    a0.y += a1.y + a2.y + a3.y;
    a0.z += a1.z + a2.z + a3.z;
    a0.w += a1.w + a2.w + a3.w;

    // combine halves: lane += lane+16
    a0.x += __shfl_down_sync(0xffffffffu, a0.x, 16);
    a0.y += __shfl_down_sync(0xffffffffu, a0.y, 16);
    a0.z += __shfl_down_sync(0xffffffffu, a0.z, 16);
    a0.w += __shfl_down_sync(0xffffffffu, a0.w, 16);

    if (half == 0) {
        float4 hv = ((const float4*)h)[(size_t)n * 16 + c];
        a0.x += hv.x; a0.y += hv.y; a0.z += hv.z; a0.w += hv.w;
        ((float4*)hsum)[(size_t)n * 16 + c] = a0;
    }
}

// ---------------------------------------------------------------------------
// Dense GEMM, 4 rows per thread (ROUND-7 SWEET SPOT: 68 regs, occ 33%,
// 65µs for gemm_in). 8 rows/thread regressed: 104 regs -> occ 22% ->
// latency-bound (round-10 lesson). unroll 2; full unroll spills (round-4).
// ---------------------------------------------------------------------------
template<int K, int NC, bool RELU, bool WRITE_HALF>
__global__ __launch_bounds__(256)
void gemm_kernel(const float* __restrict__ in,
                 const float* __restrict__ W, const float* __restrict__ b,
                 float* __restrict__ out) {
    constexpr int TPN  = NC / 4;            // threads covering one node's cols
    constexpr int GRPS = 256 / TPN;         // node-groups per block
    constexpr int NPB  = GRPS * 4;          // nodes per block

    __shared__ __align__(16) float Ws[K * NC];
    __shared__ __align__(16) float bs[NC];

    int tid = threadIdx.x;
    for (int i = tid; i < K * NC / 4; i += 256)
        ((float4*)Ws)[i] = ((const float4*)W)[i];
    if (tid < NC) bs[tid] = b[tid];
    __syncthreads();

    int cg = tid % TPN;
    int n0 = blockIdx.x * NPB + (tid / TPN) * 4;
    if (n0 >= N_NODES) return;

    int n1 = (n0 + 1 < N_NODES) ? n0 + 1 : n0;
    int n2 = (n0 + 2 < N_NODES) ? n0 + 2 : n0;
    int n3 = (n0 + 3 < N_NODES) ? n0 + 3 : n0;

    const float4* r0 = (const float4*)(in + (size_t)n0 * K);
    const float4* r1 = (const float4*)(in + (size_t)n1 * K);
    const float4* r2 = (const float4*)(in + (size_t)n2 * K);
    const float4* r3 = (const float4*)(in + (size_t)n3 * K);

    float4 bias = ((const float4*)bs)[cg];
    float4 acc0 = bias, acc1 = bias, acc2 = bias, acc3 = bias;

    #pragma unroll 2
    for (int k4 = 0; k4 < K / 4; k4++) {
        const float4* wr = (const float4*)Ws + (k4 * 4) * TPN + cg;
        float4 w0 = wr[0 * TPN];
        float4 w1 = wr[1 * TPN];
        float4 w2 = wr[2 * TPN];
        float4 w3 = wr[3 * TPN];
        float4 xv;

        xv = r0[k4];
        acc0.x += xv.x * w0.x + xv.y * w1.x + xv.z * w2.x + xv.w * w3.x;
        acc0.y += xv.x * w0.y + xv.y * w1.y + xv.z * w2.y + xv.w * w3.y;
        acc0.z += xv.x * w0.z + xv.y * w1.z + xv.z * w2.z + xv.w * w3.z;
        acc0.w += xv.x * w0.w + xv.y * w1.w + xv.z * w2.w + xv.w * w3.w;

        xv = r1[k4];
        acc1.x += xv.x * w0.x + xv.y * w1.x + xv.z * w2.x + xv.w * w3.x;
        acc1.y += xv.x * w0.y + xv.y * w1.y + xv.z * w2.y + xv.w * w3.y;
        acc1.z += xv.x * w0.z + xv.y * w1.z + xv.z * w2.z + xv.w * w3.z;
        acc1.w += xv.x * w0.w + xv.y * w1.w + xv.z * w2.w + xv.w * w3.w;

        xv = r2[k4];
        acc2.x += xv.x * w0.x + xv.y * w1.x + xv.z * w2.x + xv.w * w3.x;
        acc2.y += xv.x * w0.y + xv.y * w1.y + xv.z * w2.y + xv.w * w3.y;
        acc2.z += xv.x * w0.z + xv.y * w1.z + xv.z * w2.z + xv.w * w3.z;
        acc2.w += xv.x * w0.w + xv.y * w1.w + xv.z * w2.w + xv.w * w3.w;

        xv = r3[k4];
        acc3.x += xv.x * w0.x + xv.y * w1.x + xv.z * w2.x + xv.w * w3.x;
        acc3.y += xv.x * w0.y + xv.y * w1.y + xv.z * w2.y + xv.w * w3.y;
        acc3.z += xv.x * w0.z + xv.y * w1.z + xv.z * w2.z + xv.w * w3.z;
        acc3.w += xv.x * w0.w + xv.y * w1.w + xv.z * w2.w + xv.w * w3.w;
    }

    float4 accs[4] = {acc0, acc1, acc2, acc3};
    #pragma unroll
    for (int r = 0; r < 4; r++) {
        int n = n0 + r;
        if (n >= N_NODES) break;
        float4 a = accs[r];
        if (RELU) {
            a.x = fmaxf(a.x, 0.f);
            a.y = fmaxf(a.y, 0.f);
            a.z = fmaxf(a.z, 0.f);
            a.w = fmaxf(a.w, 0.f);
        }
        ((float4*)(out + (size_t)n * NC))[cg] = a;
        if (WRITE_HALF) {
            uint2 hp;
            __half2 p01 = __floats2half2_rn(a.x, a.y);
            __half2 p23 = __floats2half2_rn(a.z, a.w);
            hp.x = *reinterpret_cast<unsigned*>(&p01);
            hp.y = *reinterpret_cast<unsigned*>(&p23);
            ((uint2*)g_hHalf)[(size_t)n * TPN + cg] = hp;
        }
    }
}

// ---------------------------------------------------------------------------
// Launch
// ---------------------------------------------------------------------------
extern "C" void kernel_launch(void* const* d_in, const int* in_sizes, int n_in,
                              void* d_out, int out_size) {
    const float* x     = (const float*)d_in[0];
    const void*  ei    = d_in[1];
    const float* ew    = (const float*)d_in[2];
    const float* W_in  = (const float*)d_in[3];
    const float* b_in  = (const float*)d_in[4];
    const float* W_g   = (const float*)d_in[5];
    const float* b_g   = (const float*)d_in[6];
    const float* W_out = (const float*)d_in[7];
    const float* b_out = (const float*)d_in[8];
    float*       out   = (float*)d_out;

    float *hA, *hB, *hsum;
    cudaGetSymbolAddress((void**)&hA,   g_hA);
    cudaGetSymbolAddress((void**)&hB,   g_hB);
    cudaGetSymbolAddress((void**)&hsum, g_hsum);

    const int edge_blocks   = (N_EDGES + 255) / 256;
    const int gather_blocks = (N_NODES + 7) / 8;     // 1 warp per node

    const int gemm64_blocks = (N_NODES + 63) / 64;
    const int gemm32_blocks = (N_NODES + 127) / 128;

    // CSR build; gemm_in kept at capture slot #4 (control for this round)
    hist_kernel<<<edge_blocks, 256>>>(ei);
    scan1_kernel<<<NBLK, 256>>>();
    scan2_kernel<<<1, 512>>>();
    gemm_kernel<IN_DIM, HID, false, true><<<gemm64_blocks, 256>>>(x, W_in, b_in, hA);
    scan3_kernel<<<NBLK, 256>>>();
    sort_kernel<<<edge_blocks, 256>>>(ei, ew);

    float* cur = hA;
    float* nxt = hB;
    for (int l = 0; l < N_LAYERS; l++) {
        gather_kernel<<<gather_blocks, 256>>>(cur, hsum);
        bool last = (l == N_LAYERS - 1);
        if (!last)
            gemm_kernel<HID, HID, true, true><<<gemm64_blocks, 256>>>(
                hsum, W_g + (size_t)l * HID * HID, b_g + (size_t)l * HID, nxt);
        else
            gemm_kernel<HID, HID, true, false><<<gemm64_blocks, 256>>>(
                hsum, W_g + (size_t)l * HID * HID, b_g + (size_t)l * HID, nxt);
        float* t = cur; cur = nxt; nxt = t;
    }

    gemm_kernel<HID, OUT_DIM, false, false><<<gemm32_blocks, 256>>>(
        cur, W_out, b_out, out);
}

// round 15
// speedup vs baseline: 1.1324x; 1.1324x over previous
#include <cuda_runtime.h>
#include <cuda_fp16.h>

#define N_NODES 100000
#define N_EDGES 3200000
#define IN_DIM 128
#define HID 64
#define OUT_DIM 32
#define N_LAYERS 3

#define NBLK ((N_NODES + 255) / 256)   // 391 scan blocks

// Scratch: device globals (alloc-free, graph-capture safe; zero-init at load)
__device__ float  g_hA[N_NODES * HID];
__device__ float  g_hB[N_NODES * HID];
__device__ __half g_hsumH[N_NODES * HID]; // fp16 hsum (gather -> mma gemm)
__device__ __half g_hHalf[N_NODES * HID]; // fp16 copy of current h for gather
__device__ int2   g_es[N_EDGES];          // {src, weight_bits} grouped by dst
__device__ int    g_cnt[N_NODES];         // left zeroed at end of every call
__device__ int    g_rowptr[N_NODES + 1];
__device__ int    g_ofs[N_NODES];
__device__ int    g_bsum[NBLK];
__device__ int    g_boff[NBLK];

// ---------------------------------------------------------------------------
// Per-warp dtype detect: int64 elements (values < 2^31) have zero odd words.
// ---------------------------------------------------------------------------
__device__ __forceinline__ bool warp_is64(const int* ei32, int i) {
    return __all_sync(0xffffffffu, ei32[2 * i + 1] == 0);
}

__global__ void hist_kernel(const void* __restrict__ ei) {
    int i = blockIdx.x * blockDim.x + threadIdx.x;
    if (i >= N_EDGES) return;
    bool is64 = warp_is64((const int*)ei, i);
    int dst = is64 ? (int)((const long long*)ei)[(long long)N_EDGES + i]
                   : ((const int*)ei)[N_EDGES + i];
    atomicAdd(&g_cnt[dst], 1);
}

__global__ void scan1_kernel() {
    __shared__ int s[256];
    int i = blockIdx.x * 256 + threadIdx.x;
    s[threadIdx.x] = (i < N_NODES) ? g_cnt[i] : 0;
    __syncthreads();
    for (int off = 128; off > 0; off >>= 1) {
        if (threadIdx.x < off) s[threadIdx.x] += s[threadIdx.x + off];
        __syncthreads();
    }
    if (threadIdx.x == 0) g_bsum[blockIdx.x] = s[0];
}

__global__ void scan2_kernel() {
    __shared__ int s[512];
    int t = threadIdx.x;
    int v0 = (t < NBLK) ? g_bsum[t] : 0;
    s[t] = v0;
    __syncthreads();
    for (int off = 1; off < 512; off <<= 1) {
        int v = (t >= off) ? s[t - off] : 0;
        __syncthreads();
        s[t] += v;
        __syncthreads();
    }
    if (t < NBLK) g_boff[t] = s[t] - v0;   // exclusive
    if (t == 511) g_rowptr[N_NODES] = N_EDGES;
}

__global__ void scan3_kernel() {
    __shared__ int s[256];
    int t = threadIdx.x;
    int i = blockIdx.x * 256 + t;
    int v0 = (i < N_NODES) ? g_cnt[i] : 0;
    s[t] = v0;
    __syncthreads();
    for (int off = 1; off < 256; off <<= 1) {
        int v = (t >= off) ? s[t - off] : 0;
        __syncthreads();
        s[t] += v;
        __syncthreads();
    }
    if (i < N_NODES) {
        int start = g_boff[blockIdx.x] + s[t] - v0;
        g_rowptr[i] = start;
        g_ofs[i]    = start;
        g_cnt[i]    = 0;     // restore invariant for the next call/replay
    }
}

__global__ void sort_kernel(const void* __restrict__ ei,
                            const float* __restrict__ ew) {
    int i = blockIdx.x * blockDim.x + threadIdx.x;
    if (i >= N_EDGES) return;
    bool is64 = warp_is64((const int*)ei, i);
    int src, dst;
    if (is64) {
        src = (int)((const long long*)ei)[i];
        dst = (int)((const long long*)ei)[(long long)N_EDGES + i];
    } else {
        src = ((const int*)ei)[i];
        dst = ((const int*)ei)[N_EDGES + i];
    }
    int p = atomicAdd(&g_ofs[dst], 1);
    g_es[p] = make_int2(src, __float_as_int(ew[i]));
}

// ---------------------------------------------------------------------------
// Gather-aggregate: hsumH[n] = fp16( h[n] + sum_e hHalf[src_e] * w_e )
// One warp per node; round-11 loop shape (proven 78us/layer); epilogue now
// emits fp16 directly for the mma GEMM (fp32 residual read keeps accuracy).
// ---------------------------------------------------------------------------
__device__ __forceinline__ void fma_row(float4& acc, uint2 r, float w) {
    __half2 h01 = *reinterpret_cast<__half2*>(&r.x);
    __half2 h23 = *reinterpret_cast<__half2*>(&r.y);
    float2 f01 = __half22float2(h01);
    float2 f23 = __half22float2(h23);
    acc.x += f01.x * w; acc.y += f01.y * w;
    acc.z += f23.x * w; acc.w += f23.y * w;
}

__global__ __launch_bounds__(256)
void gather_kernel(const float* __restrict__ h, __half* __restrict__ hsumH) {
    int gwarp = (blockIdx.x * 256 + threadIdx.x) >> 5;
    if (gwarp >= N_NODES) return;
    int lane = threadIdx.x & 31;
    int half = lane >> 4;
    int c    = lane & 15;
    int n    = gwarp;

    int beg = g_rowptr[n];
    int cnt = g_rowptr[n + 1] - beg;

    const uint2* hh = (const uint2*)g_hHalf;   // 16 uint2 per row

    float4 a0 = make_float4(0.f, 0.f, 0.f, 0.f);
    float4 a1 = make_float4(0.f, 0.f, 0.f, 0.f);

    for (int base = 0; base < cnt; base += 32) {
        int2 m = (base + lane < cnt) ? g_es[beg + base + lane]
                                     : make_int2(0, 0);   // w=0 padding
        #pragma unroll
        for (int j = 0; j < 32; j += 4) {
            int   s0 = __shfl_sync(0xffffffffu, m.x, j + half);
            float w0 = __int_as_float(__shfl_sync(0xffffffffu, m.y, j + half));
            int   s1 = __shfl_sync(0xffffffffu, m.x, j + 2 + half);
            float w1 = __int_as_float(__shfl_sync(0xffffffffu, m.y, j + 2 + half));
            uint2 r0 = hh[(size_t)s0 * 16 + c];
            uint2 r1 = hh[(size_t)s1 * 16 + c];
            fma_row(a0, r0, w0);
            fma_row(a1, r1, w1);
        }
    }

    a0.x += a1.x; a0.y += a1.y; a0.z += a1.z; a0.w += a1.w;

    a0.x += __shfl_down_sync(0xffffffffu, a0.x, 16);
    a0.y += __shfl_down_sync(0xffffffffu, a0.y, 16);
    a0.z += __shfl_down_sync(0xffffffffu, a0.z, 16);
    a0.w += __shfl_down_sync(0xffffffffu, a0.w, 16);

    if (half == 0) {
        float4 hv = ((const float4*)h)[(size_t)n * 16 + c];
        a0.x += hv.x; a0.y += hv.y; a0.z += hv.z; a0.w += hv.w;
        __half2 p01 = __floats2half2_rn(a0.x, a0.y);
        __half2 p23 = __floats2half2_rn(a0.z, a0.w);
        uint2 hp;
        hp.x = *reinterpret_cast<unsigned*>(&p01);
        hp.y = *reinterpret_cast<unsigned*>(&p23);
        ((uint2*)hsumH)[(size_t)n * 16 + c] = hp;
    }
}

// ---------------------------------------------------------------------------
// Tensor-core HID GEMM: out[n,:64] = relu( hsumH[n,:64] @ W[64,64] + b ),
// also writes fp16 copy to g_hHalf. mma.sync.m16n8k16 f16xf16->f32.
// Block = 128 threads (4 warps) = 64 nodes; warp computes 16 nodes x 64 cols.
// ---------------------------------------------------------------------------
#define APAD 72   // smem row stride in halfs (64 + 8 pad -> conflict-free ldsm)

__device__ __forceinline__ void ldsm_x4(unsigned* r, unsigned addr) {
    asm volatile("ldmatrix.sync.aligned.m8n8.x4.shared.b16 {%0,%1,%2,%3}, [%4];"
                 : "=r"(r[0]), "=r"(r[1]), "=r"(r[2]), "=r"(r[3]) : "r"(addr));
}
__device__ __forceinline__ void ldsm_x4_t(unsigned* r, unsigned addr) {
    asm volatile("ldmatrix.sync.aligned.m8n8.x4.trans.shared.b16 {%0,%1,%2,%3}, [%4];"
                 : "=r"(r[0]), "=r"(r[1]), "=r"(r[2]), "=r"(r[3]) : "r"(addr));
}
__device__ __forceinline__ void mma16816(float* c, const unsigned* a,
                                         unsigned b0, unsigned b1) {
    asm volatile("mma.sync.aligned.m16n8k16.row.col.f32.f16.f16.f32 "
                 "{%0,%1,%2,%3}, {%4,%5,%6,%7}, {%8,%9}, {%0,%1,%2,%3};"
                 : "+f"(c[0]), "+f"(c[1]), "+f"(c[2]), "+f"(c[3])
                 : "r"(a[0]), "r"(a[1]), "r"(a[2]), "r"(a[3]),
                   "r"(b0), "r"(b1));
}

__global__ __launch_bounds__(128)
void mma_gemm64_kernel(const __half* __restrict__ inH,
                       const float* __restrict__ W,   // [64][64] row-major
                       const float* __restrict__ b,
                       float* __restrict__ out) {
    __shared__ __align__(16) __half As[64 * APAD];
    __shared__ __align__(16) __half Bs[64 * APAD];
    __shared__ float bsm[64];

    int tid = threadIdx.x;
    int n0  = blockIdx.x * 64;

    // Load A tile (64 rows x 64 halfs), zero-padding rows past N_NODES.
    {
        const uint2* src = (const uint2*)(inH + (size_t)n0 * HID); // 16 uint2/row
        for (int u = tid; u < 64 * 16; u += 128) {
            int row = u >> 4, c4 = u & 15;
            uint2 v = (n0 + row < N_NODES) ? src[u] : make_uint2(0u, 0u);
            *(uint2*)&As[row * APAD + c4 * 4] = v;
        }
    }
    // Load + convert W
    for (int e = tid; e < 64 * 64; e += 128) {
        int k = e >> 6, n = e & 63;
        Bs[k * APAD + n] = __float2half(W[e]);
    }
    if (tid < 64) bsm[tid] = b[tid];
    __syncthreads();

    int warp = tid >> 5;
    int lane = tid & 31;
    int wr   = warp * 16;          // warp's 16 rows
    int grp  = lane >> 2;
    int ctg  = lane & 3;

    unsigned sA = (unsigned)__cvta_generic_to_shared(As);
    unsigned sB = (unsigned)__cvta_generic_to_shared(Bs);

    float acc[8][4];
    #pragma unroll
    for (int nn = 0; nn < 8; nn++)
        #pragma unroll
        for (int q = 0; q < 4; q++) acc[nn][q] = 0.f;

    int j = lane >> 3, r = lane & 7;

    #pragma unroll
    for (int ks = 0; ks < 4; ks++) {
        int kk = ks * 16;
        // A frag: m0=(rows wr..+7, k kk), m1=(+8 rows), m2=(k+8), m3=(+8,+8)
        unsigned a[4];
        {
            int arow = wr + ((j & 1) << 3) + r;
            int acol = kk + ((j >> 1) << 3);
            ldsm_x4(a, sA + (unsigned)(arow * APAD + acol) * 2u);
        }
        #pragma unroll
        for (int np = 0; np < 4; np++) {
            // B frags for n-steps 2np, 2np+1 via x4.trans:
            // m0=(k kk..+7, n 16np..+7) m1=(k+8, same n) m2,m3 = n+8
            unsigned bm[4];
            int brow = kk + ((j & 1) << 3) + r;
            int bcol = np * 16 + ((j >> 1) << 3);
            ldsm_x4_t(bm, sB + (unsigned)(brow * APAD + bcol) * 2u);
            mma16816(acc[2 * np],     a, bm[0], bm[1]);
            mma16816(acc[2 * np + 1], a, bm[2], bm[3]);
        }
    }

    // Epilogue: bias + relu; write fp32 out + fp16 hHalf.
    int row0 = n0 + wr + grp;
    int row1 = row0 + 8;
    #pragma unroll
    for (int nn = 0; nn < 8; nn++) {
        int col = nn * 8 + ctg * 2;
        float bx = bsm[col], by = bsm[col + 1];
        float v0 = fmaxf(acc[nn][0] + bx, 0.f);
        float v1 = fmaxf(acc[nn][1] + by, 0.f);
        float v2 = fmaxf(acc[nn][2] + bx, 0.f);
        float v3 = fmaxf(acc[nn][3] + by, 0.f);
        if (row0 < N_NODES) {
            ((float2*)(out + (size_t)row0 * HID))[col >> 1] = make_float2(v0, v1);
            __half2 p = __floats2half2_rn(v0, v1);
            ((__half2*)(g_hHalf + (size_t)row0 * HID))[col >> 1] = p;
        }
        if (row1 < N_NODES) {
            ((float2*)(out + (size_t)row1 * HID))[col >> 1] = make_float2(v2, v3);
            __half2 p = __floats2half2_rn(v2, v3);
            ((__half2*)(g_hHalf + (size_t)row1 * HID))[col >> 1] = p;
        }
    }
}

// ---------------------------------------------------------------------------
// Dense fp32 GEMM, 4 rows/thread (round-7 sweet spot). Used for in/out proj.
// ---------------------------------------------------------------------------
template<int K, int NC, bool RELU, bool WRITE_HALF>
__global__ __launch_bounds__(256)
void gemm_kernel(const float* __restrict__ in,
                 const float* __restrict__ W, const float* __restrict__ b,
                 float* __restrict__ out) {
    constexpr int TPN  = NC / 4;
    constexpr int GRPS = 256 / TPN;
    constexpr int NPB  = GRPS * 4;

    __shared__ __align__(16) float Ws[K * NC];
    __shared__ __align__(16) float bs[NC];

    int tid = threadIdx.x;
    for (int i = tid; i < K * NC / 4; i += 256)
        ((float4*)Ws)[i] = ((const float4*)W)[i];
    if (tid < NC) bs[tid] = b[tid];
    __syncthreads();

    int cg = tid % TPN;
    int n0 = blockIdx.x * NPB + (tid / TPN) * 4;
    if (n0 >= N_NODES) return;

    int n1 = (n0 + 1 < N_NODES) ? n0 + 1 : n0;
    int n2 = (n0 + 2 < N_NODES) ? n0 + 2 : n0;
    int n3 = (n0 + 3 < N_NODES) ? n0 + 3 : n0;

    const float4* r0 = (const float4*)(in + (size_t)n0 * K);
    const float4* r1 = (const float4*)(in + (size_t)n1 * K);
    const float4* r2 = (const float4*)(in + (size_t)n2 * K);
    const float4* r3 = (const float4*)(in + (size_t)n3 * K);

    float4 bias = ((const float4*)bs)[cg];
    float4 acc0 = bias, acc1 = bias, acc2 = bias, acc3 = bias;

    #pragma unroll 2
    for (int k4 = 0; k4 < K / 4; k4++) {
        const float4* wr = (const float4*)Ws + (k4 * 4) * TPN + cg;
        float4 w0 = wr[0 * TPN];
        float4 w1 = wr[1 * TPN];
        float4 w2 = wr[2 * TPN];
        float4 w3 = wr[3 * TPN];
        float4 xv;

        xv = r0[k4];
        acc0.x += xv.x * w0.x + xv.y * w1.x + xv.z * w2.x + xv.w * w3.x;
        acc0.y += xv.x * w0.y + xv.y * w1.y + xv.z * w2.y + xv.w * w3.y;
        acc0.z += xv.x * w0.z + xv.y * w1.z + xv.z * w2.z + xv.w * w3.z;
        acc0.w += xv.x * w0.w + xv.y * w1.w + xv.z * w2.w + xv.w * w3.w;

        xv = r1[k4];
        acc1.x += xv.x * w0.x + xv.y * w1.x + xv.z * w2.x + xv.w * w3.x;
        acc1.y += xv.x * w0.y + xv.y * w1.y + xv.z * w2.y + xv.w * w3.y;
        acc1.z += xv.x * w0.z + xv.y * w1.z + xv.z * w2.z + xv.w * w3.z;
        acc1.w += xv.x * w0.w + xv.y * w1.w + xv.z * w2.w + xv.w * w3.w;

        xv = r2[k4];
        acc2.x += xv.x * w0.x + xv.y * w1.x + xv.z * w2.x + xv.w * w3.x;
        acc2.y += xv.x * w0.y + xv.y * w1.y + xv.z * w2.y + xv.w * w3.y;
        acc2.z += xv.x * w0.z + xv.y * w1.z + xv.z * w2.z + xv.w * w3.z;
        acc2.w += xv.x * w0.w + xv.y * w1.w + xv.z * w2.w + xv.w * w3.w;

        xv = r3[k4];
        acc3.x += xv.x * w0.x + xv.y * w1.x + xv.z * w2.x + xv.w * w3.x;
        acc3.y += xv.x * w0.y + xv.y * w1.y + xv.z * w2.y + xv.w * w3.y;
        acc3.z += xv.x * w0.z + xv.y * w1.z + xv.z * w2.z + xv.w * w3.z;
        acc3.w += xv.x * w0.w + xv.y * w1.w + xv.z * w2.w + xv.w * w3.w;
    }

    float4 accs[4] = {acc0, acc1, acc2, acc3};
    #pragma unroll
    for (int r = 0; r < 4; r++) {
        int n = n0 + r;
        if (n >= N_NODES) break;
        float4 a = accs[r];
        if (RELU) {
            a.x = fmaxf(a.x, 0.f);
            a.y = fmaxf(a.y, 0.f);
            a.z = fmaxf(a.z, 0.f);
            a.w = fmaxf(a.w, 0.f);
        }
        ((float4*)(out + (size_t)n * NC))[cg] = a;
        if (WRITE_HALF) {
            uint2 hp;
            __half2 p01 = __floats2half2_rn(a.x, a.y);
            __half2 p23 = __floats2half2_rn(a.z, a.w);
            hp.x = *reinterpret_cast<unsigned*>(&p01);
            hp.y = *reinterpret_cast<unsigned*>(&p23);
            ((uint2*)g_hHalf)[(size_t)n * TPN + cg] = hp;
        }
    }
}

// ---------------------------------------------------------------------------
// Launch
// ---------------------------------------------------------------------------
extern "C" void kernel_launch(void* const* d_in, const int* in_sizes, int n_in,
                              void* d_out, int out_size) {
    const float* x     = (const float*)d_in[0];
    const void*  ei    = d_in[1];
    const float* ew    = (const float*)d_in[2];
    const float* W_in  = (const float*)d_in[3];
    const float* b_in  = (const float*)d_in[4];
    const float* W_g   = (const float*)d_in[5];
    const float* b_g   = (const float*)d_in[6];
    const float* W_out = (const float*)d_in[7];
    const float* b_out = (const float*)d_in[8];
    float*       out   = (float*)d_out;

    float  *hA, *hB;
    __half *hsumH;
    cudaGetSymbolAddress((void**)&hA,    g_hA);
    cudaGetSymbolAddress((void**)&hB,    g_hB);
    cudaGetSymbolAddress((void**)&hsumH, g_hsumH);

    const int edge_blocks   = (N_EDGES + 255) / 256;
    const int gather_blocks = (N_NODES + 7) / 8;     // 1 warp per node
    const int gemm64_blocks = (N_NODES + 63) / 64;
    const int gemm32_blocks = (N_NODES + 127) / 128;
    const int mma_blocks    = (N_NODES + 63) / 64;

    // CSR build; gemm_in kept at capture slot #4 (control)
    hist_kernel<<<edge_blocks, 256>>>(ei);
    scan1_kernel<<<NBLK, 256>>>();
    scan2_kernel<<<1, 512>>>();
    gemm_kernel<IN_DIM, HID, false, true><<<gemm64_blocks, 256>>>(x, W_in, b_in, hA);
    scan3_kernel<<<NBLK, 256>>>();
    sort_kernel<<<edge_blocks, 256>>>(ei, ew);

    float* cur = hA;
    float* nxt = hB;
    for (int l = 0; l < N_LAYERS; l++) {
        gather_kernel<<<gather_blocks, 256>>>(cur, hsumH);
        mma_gemm64_kernel<<<mma_blocks, 128>>>(
            hsumH, W_g + (size_t)l * HID * HID, b_g + (size_t)l * HID, nxt);
        float* t = cur; cur = nxt; nxt = t;
    }

    gemm_kernel<HID, OUT_DIM, false, false><<<gemm32_blocks, 256>>>(
        cur, W_out, b_out, out);
}

// round 16
// speedup vs baseline: 1.2043x; 1.0635x over previous
#include <cuda_runtime.h>
#include <cuda_fp16.h>

#define N_NODES 100000
#define N_EDGES 3200000
#define IN_DIM 128
#define HID 64
#define OUT_DIM 32
#define N_LAYERS 3

#define NBLK ((N_NODES + 255) / 256)   // 391 scan blocks

// Scratch: device globals (alloc-free, graph-capture safe; zero-init at load)
__device__ float  g_hA[N_NODES * HID];
__device__ float  g_hB[N_NODES * HID];
__device__ __half g_xH[N_NODES * IN_DIM]; // fp16 copy of x for mma input proj
__device__ __half g_hsumH[N_NODES * HID]; // fp16 hsum (gather -> mma gemm)
__device__ __half g_hHalf[N_NODES * HID]; // fp16 copy of current h for gather
__device__ int2   g_es[N_EDGES];          // {src, weight_bits} grouped by dst
__device__ int    g_cnt[N_NODES];         // left zeroed at end of every call
__device__ int    g_rowptr[N_NODES + 1];
__device__ int    g_ofs[N_NODES];
__device__ int    g_bsum[NBLK];
__device__ int    g_boff[NBLK];

// ---------------------------------------------------------------------------
// Per-warp dtype detect: int64 elements (values < 2^31) have zero odd words.
// ---------------------------------------------------------------------------
__device__ __forceinline__ bool warp_is64(const int* ei32, int i) {
    return __all_sync(0xffffffffu, ei32[2 * i + 1] == 0);
}

__global__ void hist_kernel(const void* __restrict__ ei) {
    int i = blockIdx.x * blockDim.x + threadIdx.x;
    if (i >= N_EDGES) return;
    bool is64 = warp_is64((const int*)ei, i);
    int dst = is64 ? (int)((const long long*)ei)[(long long)N_EDGES + i]
                   : ((const int*)ei)[N_EDGES + i];
    atomicAdd(&g_cnt[dst], 1);
}

__global__ void scan1_kernel() {
    __shared__ int s[256];
    int i = blockIdx.x * 256 + threadIdx.x;
    s[threadIdx.x] = (i < N_NODES) ? g_cnt[i] : 0;
    __syncthreads();
    for (int off = 128; off > 0; off >>= 1) {
        if (threadIdx.x < off) s[threadIdx.x] += s[threadIdx.x + off];
        __syncthreads();
    }
    if (threadIdx.x == 0) g_bsum[blockIdx.x] = s[0];
}

__global__ void scan2_kernel() {
    __shared__ int s[512];
    int t = threadIdx.x;
    int v0 = (t < NBLK) ? g_bsum[t] : 0;
    s[t] = v0;
    __syncthreads();
    for (int off = 1; off < 512; off <<= 1) {
        int v = (t >= off) ? s[t - off] : 0;
        __syncthreads();
        s[t] += v;
        __syncthreads();
    }
    if (t < NBLK) g_boff[t] = s[t] - v0;   // exclusive
    if (t == 511) g_rowptr[N_NODES] = N_EDGES;
}

__global__ void scan3_kernel() {
    __shared__ int s[256];
    int t = threadIdx.x;
    int i = blockIdx.x * 256 + t;
    int v0 = (i < N_NODES) ? g_cnt[i] : 0;
    s[t] = v0;
    __syncthreads();
    for (int off = 1; off < 256; off <<= 1) {
        int v = (t >= off) ? s[t - off] : 0;
        __syncthreads();
        s[t] += v;
        __syncthreads();
    }
    if (i < N_NODES) {
        int start = g_boff[blockIdx.x] + s[t] - v0;
        g_rowptr[i] = start;
        g_ofs[i]    = start;
        g_cnt[i]    = 0;     // restore invariant for the next call/replay
    }
}

__global__ void sort_kernel(const void* __restrict__ ei,
                            const float* __restrict__ ew) {
    int i = blockIdx.x * blockDim.x + threadIdx.x;
    if (i >= N_EDGES) return;
    bool is64 = warp_is64((const int*)ei, i);
    int src, dst;
    if (is64) {
        src = (int)((const long long*)ei)[i];
        dst = (int)((const long long*)ei)[(long long)N_EDGES + i];
    } else {
        src = ((const int*)ei)[i];
        dst = ((const int*)ei)[N_EDGES + i];
    }
    int p = atomicAdd(&g_ofs[dst], 1);
    g_es[p] = make_int2(src, __float_as_int(ew[i]));
}

// ---------------------------------------------------------------------------
// x -> fp16 (for tensor-core input projection)
// ---------------------------------------------------------------------------
__global__ void convert_x_kernel(const float* __restrict__ x) {
    int i = blockIdx.x * blockDim.x + threadIdx.x;
    if (i >= N_NODES * IN_DIM / 4) return;
    float4 v = ((const float4*)x)[i];
    __half2 p01 = __floats2half2_rn(v.x, v.y);
    __half2 p23 = __floats2half2_rn(v.z, v.w);
    uint2 hp;
    hp.x = *reinterpret_cast<unsigned*>(&p01);
    hp.y = *reinterpret_cast<unsigned*>(&p23);
    ((uint2*)g_xH)[i] = hp;
}

// ---------------------------------------------------------------------------
// Gather-aggregate: hsumH[n] = fp16( h[n] + sum_e hHalf[src_e] * w_e )
// 64-thread blocks (2 warps): intra-block imbalance max-of-2 (vs max-of-8).
// Full 32-edge tiles via coalesced load + shfl broadcast; remainder at
// 2-edge granularity (kills the 32-edge tile-quantization waste).
// ---------------------------------------------------------------------------
__device__ __forceinline__ void fma_row(float4& acc, uint2 r, float w) {
    __half2 h01 = *reinterpret_cast<__half2*>(&r.x);
    __half2 h23 = *reinterpret_cast<__half2*>(&r.y);
    float2 f01 = __half22float2(h01);
    float2 f23 = __half22float2(h23);
    acc.x += f01.x * w; acc.y += f01.y * w;
    acc.z += f23.x * w; acc.w += f23.y * w;
}

__global__ __launch_bounds__(64)
void gather_kernel(const float* __restrict__ h, __half* __restrict__ hsumH) {
    int n = blockIdx.x * 2 + (threadIdx.x >> 5);
    if (n >= N_NODES) return;
    int lane = threadIdx.x & 31;
    int half = lane >> 4;
    int c    = lane & 15;

    int beg = g_rowptr[n];
    int cnt = g_rowptr[n + 1] - beg;
    int full = cnt & ~31;

    const uint2* hh = (const uint2*)g_hHalf;   // 16 uint2 per row

    float4 a0 = make_float4(0.f, 0.f, 0.f, 0.f);
    float4 a1 = make_float4(0.f, 0.f, 0.f, 0.f);

    for (int base = 0; base < full; base += 32) {
        int2 m = g_es[beg + base + lane];
        #pragma unroll
        for (int j = 0; j < 32; j += 4) {
            int   s0 = __shfl_sync(0xffffffffu, m.x, j + half);
            float w0 = __int_as_float(__shfl_sync(0xffffffffu, m.y, j + half));
            int   s1 = __shfl_sync(0xffffffffu, m.x, j + 2 + half);
            float w1 = __int_as_float(__shfl_sync(0xffffffffu, m.y, j + 2 + half));
            uint2 r0 = hh[(size_t)s0 * 16 + c];
            uint2 r1 = hh[(size_t)s1 * 16 + c];
            fma_row(a0, r0, w0);
            fma_row(a1, r1, w1);
        }
    }
    // remainder (<32 edges): halves take even/odd, 2-edge granularity
    for (int e = beg + full + half; e < beg + cnt; e += 2) {
        int2 m = g_es[e];                       // 16-lane broadcast load
        uint2 r = hh[(size_t)m.x * 16 + c];
        fma_row(a0, r, __int_as_float(m.y));
    }

    a0.x += a1.x; a0.y += a1.y; a0.z += a1.z; a0.w += a1.w;

    a0.x += __shfl_down_sync(0xffffffffu, a0.x, 16);
    a0.y += __shfl_down_sync(0xffffffffu, a0.y, 16);
    a0.z += __shfl_down_sync(0xffffffffu, a0.z, 16);
    a0.w += __shfl_down_sync(0xffffffffu, a0.w, 16);

    if (half == 0) {
        float4 hv = ((const float4*)h)[(size_t)n * 16 + c];
        a0.x += hv.x; a0.y += hv.y; a0.z += hv.z; a0.w += hv.w;
        __half2 p01 = __floats2half2_rn(a0.x, a0.y);
        __half2 p23 = __floats2half2_rn(a0.z, a0.w);
        uint2 hp;
        hp.x = *reinterpret_cast<unsigned*>(&p01);
        hp.y = *reinterpret_cast<unsigned*>(&p23);
        ((uint2*)hsumH)[(size_t)n * 16 + c] = hp;
    }
}

// ---------------------------------------------------------------------------
// Tensor-core GEMM: out[n,:64] = act( inH[n,:K] @ W[K,64] + b ), fp32 out +
// fp16 copy to g_hHalf. mma.sync.m16n8k16 f16xf16->f32.
// Block = 128 threads (4 warps) = 64 nodes; warp computes 16 nodes x 64 cols.
// ---------------------------------------------------------------------------
#define BPAD 72   // B smem row stride in halfs

__device__ __forceinline__ void ldsm_x4(unsigned* r, unsigned addr) {
    asm volatile("ldmatrix.sync.aligned.m8n8.x4.shared.b16 {%0,%1,%2,%3}, [%4];"
                 : "=r"(r[0]), "=r"(r[1]), "=r"(r[2]), "=r"(r[3]) : "r"(addr));
}
__device__ __forceinline__ void ldsm_x4_t(unsigned* r, unsigned addr) {
    asm volatile("ldmatrix.sync.aligned.m8n8.x4.trans.shared.b16 {%0,%1,%2,%3}, [%4];"
                 : "=r"(r[0]), "=r"(r[1]), "=r"(r[2]), "=r"(r[3]) : "r"(addr));
}
__device__ __forceinline__ void mma16816(float* c, const unsigned* a,
                                         unsigned b0, unsigned b1) {
    asm volatile("mma.sync.aligned.m16n8k16.row.col.f32.f16.f16.f32 "
                 "{%0,%1,%2,%3}, {%4,%5,%6,%7}, {%8,%9}, {%0,%1,%2,%3};"
                 : "+f"(c[0]), "+f"(c[1]), "+f"(c[2]), "+f"(c[3])
                 : "r"(a[0]), "r"(a[1]), "r"(a[2]), "r"(a[3]),
                   "r"(b0), "r"(b1));
}

template<int K, bool RELU>
__global__ __launch_bounds__(128)
void mma_gemm_kernel(const __half* __restrict__ inH,
                     const float* __restrict__ W,   // [K][64] row-major
                     const float* __restrict__ b,
                     float* __restrict__ out) {
    constexpr int APAD = K + 8;   // A smem row stride in halfs
    __shared__ __align__(16) __half As[64 * APAD];
    __shared__ __align__(16) __half Bs[K * BPAD];
    __shared__ float bsm[64];

    int tid = threadIdx.x;
    int n0  = blockIdx.x * 64;

    // Load A tile (64 rows x K halfs), zero-padding rows past N_NODES.
    {
        const uint2* src = (const uint2*)(inH + (size_t)n0 * K); // K/4 uint2/row
        for (int u = tid; u < 64 * (K / 4); u += 128) {
            int row = u / (K / 4), c4 = u % (K / 4);
            uint2 v = (n0 + row < N_NODES) ? src[u] : make_uint2(0u, 0u);
            *(uint2*)&As[row * APAD + c4 * 4] = v;
        }
    }
    // Load + convert W
    for (int e = tid; e < K * 64; e += 128) {
        int k = e >> 6, n = e & 63;
        Bs[k * BPAD + n] = __float2half(W[e]);
    }
    if (tid < 64) bsm[tid] = b[tid];
    __syncthreads();

    int warp = tid >> 5;
    int lane = tid & 31;
    int wr   = warp * 16;          // warp's 16 rows
    int grp  = lane >> 2;
    int ctg  = lane & 3;

    unsigned sA = (unsigned)__cvta_generic_to_shared(As);
    unsigned sB = (unsigned)__cvta_generic_to_shared(Bs);

    float acc[8][4];
    #pragma unroll
    for (int nn = 0; nn < 8; nn++)
        #pragma unroll
        for (int q = 0; q < 4; q++) acc[nn][q] = 0.f;

    int j = lane >> 3, r = lane & 7;

    #pragma unroll
    for (int ks = 0; ks < K / 16; ks++) {
        int kk = ks * 16;
        unsigned a[4];
        {
            int arow = wr + ((j & 1) << 3) + r;
            int acol = kk + ((j >> 1) << 3);
            ldsm_x4(a, sA + (unsigned)(arow * APAD + acol) * 2u);
        }
        #pragma unroll
        for (int np = 0; np < 4; np++) {
            unsigned bm[4];
            int brow = kk + ((j & 1) << 3) + r;
            int bcol = np * 16 + ((j >> 1) << 3);
            ldsm_x4_t(bm, sB + (unsigned)(brow * BPAD + bcol) * 2u);
            mma16816(acc[2 * np],     a, bm[0], bm[1]);
            mma16816(acc[2 * np + 1], a, bm[2], bm[3]);
        }
    }

    // Epilogue: bias (+relu); write fp32 out + fp16 hHalf.
    int row0 = n0 + wr + grp;
    int row1 = row0 + 8;
    #pragma unroll
    for (int nn = 0; nn < 8; nn++) {
        int col = nn * 8 + ctg * 2;
        float bx = bsm[col], by = bsm[col + 1];
        float v0 = acc[nn][0] + bx, v1 = acc[nn][1] + by;
        float v2 = acc[nn][2] + bx, v3 = acc[nn][3] + by;
        if (RELU) {
            v0 = fmaxf(v0, 0.f); v1 = fmaxf(v1, 0.f);
            v2 = fmaxf(v2, 0.f); v3 = fmaxf(v3, 0.f);
        }
        if (row0 < N_NODES) {
            ((float2*)(out + (size_t)row0 * HID))[col >> 1] = make_float2(v0, v1);
            __half2 p = __floats2half2_rn(v0, v1);
            ((__half2*)(g_hHalf + (size_t)row0 * HID))[col >> 1] = p;
        }
        if (row1 < N_NODES) {
            ((float2*)(out + (size_t)row1 * HID))[col >> 1] = make_float2(v2, v3);
            __half2 p = __floats2half2_rn(v2, v3);
            ((__half2*)(g_hHalf + (size_t)row1 * HID))[col >> 1] = p;
        }
    }
}

// ---------------------------------------------------------------------------
// Dense fp32 GEMM, 4 rows/thread (round-7 sweet spot). Used for out proj.
// ---------------------------------------------------------------------------
template<int K, int NC, bool RELU>
__global__ __launch_bounds__(256)
void gemm_kernel(const float* __restrict__ in,
                 const float* __restrict__ W, const float* __restrict__ b,
                 float* __restrict__ out) {
    constexpr int TPN  = NC / 4;
    constexpr int GRPS = 256 / TPN;
    constexpr int NPB  = GRPS * 4;

    __shared__ __align__(16) float Ws[K * NC];
    __shared__ __align__(16) float bs[NC];

    int tid = threadIdx.x;
    for (int i = tid; i < K * NC / 4; i += 256)
        ((float4*)Ws)[i] = ((const float4*)W)[i];
    if (tid < NC) bs[tid] = b[tid];
    __syncthreads();

    int cg = tid % TPN;
    int n0 = blockIdx.x * NPB + (tid / TPN) * 4;
    if (n0 >= N_NODES) return;

    int n1 = (n0 + 1 < N_NODES) ? n0 + 1 : n0;
    int n2 = (n0 + 2 < N_NODES) ? n0 + 2 : n0;
    int n3 = (n0 + 3 < N_NODES) ? n0 + 3 : n0;

    const float4* r0 = (const float4*)(in + (size_t)n0 * K);
    const float4* r1 = (const float4*)(in + (size_t)n1 * K);
    const float4* r2 = (const float4*)(in + (size_t)n2 * K);
    const float4* r3 = (const float4*)(in + (size_t)n3 * K);

    float4 bias = ((const float4*)bs)[cg];
    float4 acc0 = bias, acc1 = bias, acc2 = bias, acc3 = bias;

    #pragma unroll 2
    for (int k4 = 0; k4 < K / 4; k4++) {
        const float4* wr = (const float4*)Ws + (k4 * 4) * TPN + cg;
        float4 w0 = wr[0 * TPN];
        float4 w1 = wr[1 * TPN];
        float4 w2 = wr[2 * TPN];
        float4 w3 = wr[3 * TPN];
        float4 xv;

        xv = r0[k4];
        acc0.x += xv.x * w0.x + xv.y * w1.x + xv.z * w2.x + xv.w * w3.x;
        acc0.y += xv.x * w0.y + xv.y * w1.y + xv.z * w2.y + xv.w * w3.y;
        acc0.z += xv.x * w0.z + xv.y * w1.z + xv.z * w2.z + xv.w * w3.z;
        acc0.w += xv.x * w0.w + xv.y * w1.w + xv.z * w2.w + xv.w * w3.w;

        xv = r1[k4];
        acc1.x += xv.x * w0.x + xv.y * w1.x + xv.z * w2.x + xv.w * w3.x;
        acc1.y += xv.x * w0.y + xv.y * w1.y + xv.z * w2.y + xv.w * w3.y;
        acc1.z += xv.x * w0.z + xv.y * w1.z + xv.z * w2.z + xv.w * w3.z;
        acc1.w += xv.x * w0.w + xv.y * w1.w + xv.z * w2.w + xv.w * w3.w;

        xv = r2[k4];
        acc2.x += xv.x * w0.x + xv.y * w1.x + xv.z * w2.x + xv.w * w3.x;
        acc2.y += xv.x * w0.y + xv.y * w1.y + xv.z * w2.y + xv.w * w3.y;
        acc2.z += xv.x * w0.z + xv.y * w1.z + xv.z * w2.z + xv.w * w3.z;
        acc2.w += xv.x * w0.w + xv.y * w1.w + xv.z * w2.w + xv.w * w3.w;

        xv = r3[k4];
        acc3.x += xv.x * w0.x + xv.y * w1.x + xv.z * w2.x + xv.w * w3.x;
        acc3.y += xv.x * w0.y + xv.y * w1.y + xv.z * w2.y + xv.w * w3.y;
        acc3.z += xv.x * w0.z + xv.y * w1.z + xv.z * w2.z + xv.w * w3.z;
        acc3.w += xv.x * w0.w + xv.y * w1.w + xv.z * w2.w + xv.w * w3.w;
    }

    float4 accs[4] = {acc0, acc1, acc2, acc3};
    #pragma unroll
    for (int r = 0; r < 4; r++) {
        int n = n0 + r;
        if (n >= N_NODES) break;
        float4 a = accs[r];
        if (RELU) {
            a.x = fmaxf(a.x, 0.f);
            a.y = fmaxf(a.y, 0.f);
            a.z = fmaxf(a.z, 0.f);
            a.w = fmaxf(a.w, 0.f);
        }
        ((float4*)(out + (size_t)n * NC))[cg] = a;
    }
}

// ---------------------------------------------------------------------------
// Launch
// ---------------------------------------------------------------------------
extern "C" void kernel_launch(void* const* d_in, const int* in_sizes, int n_in,
                              void* d_out, int out_size) {
    const float* x     = (const float*)d_in[0];
    const void*  ei    = d_in[1];
    const float* ew    = (const float*)d_in[2];
    const float* W_in  = (const float*)d_in[3];
    const float* b_in  = (const float*)d_in[4];
    const float* W_g   = (const float*)d_in[5];
    const float* b_g   = (const float*)d_in[6];
    const float* W_out = (const float*)d_in[7];
    const float* b_out = (const float*)d_in[8];
    float*       out   = (float*)d_out;

    float  *hA, *hB;
    __half *hsumH, *xH;
    cudaGetSymbolAddress((void**)&hA,    g_hA);
    cudaGetSymbolAddress((void**)&hB,    g_hB);
    cudaGetSymbolAddress((void**)&hsumH, g_hsumH);
    cudaGetSymbolAddress((void**)&xH,    g_xH);

    const int edge_blocks   = (N_EDGES + 255) / 256;
    const int gather_blocks = (N_NODES + 1) / 2;     // 2 warps per block
    const int conv_blocks   = (N_NODES * IN_DIM / 4 + 255) / 256;
    const int gemm32_blocks = (N_NODES + 127) / 128;
    const int mma_blocks    = (N_NODES + 63) / 64;

    // CSR build + input proj; mma_gemm<128> at capture slot #4
    convert_x_kernel<<<conv_blocks, 256>>>(x);
    hist_kernel<<<edge_blocks, 256>>>(ei);
    scan1_kernel<<<NBLK, 256>>>();
    mma_gemm_kernel<IN_DIM, false><<<mma_blocks, 128>>>(xH, W_in, b_in, hA);
    scan2_kernel<<<1, 512>>>();
    scan3_kernel<<<NBLK, 256>>>();
    sort_kernel<<<edge_blocks, 256>>>(ei, ew);

    float* cur = hA;
    float* nxt = hB;
    for (int l = 0; l < N_LAYERS; l++) {
        gather_kernel<<<gather_blocks, 64>>>(cur, hsumH);
        mma_gemm_kernel<HID, true><<<mma_blocks, 128>>>(
            hsumH, W_g + (size_t)l * HID * HID, b_g + (size_t)l * HID, nxt);
        float* t = cur; cur = nxt; nxt = t;
    }

    gemm_kernel<HID, OUT_DIM, false><<<gemm32_blocks, 256>>>(
        cur, W_out, b_out, out);
}